// round 8
// baseline (speedup 1.0000x reference)
#include <cuda_runtime.h>
#include <cuda_bf16.h>
#include <cstdint>
#include <math.h>

// Problem constants
#define BATCH 2
#define SEQ   2048
#define CMODEL 1024
#define NHEAD 16
#define HDIM  64
#define MROWS (BATCH * SEQ)   // 4096

// ---------------------------------------------------------------------------
// Scratch
// ---------------------------------------------------------------------------
__device__ float    g_q[MROWS * CMODEL];
__device__ float    g_k[MROWS * CMODEL];
__device__ float    g_v[MROWS * CMODEL];
__device__ uint32_t g_xp[MROWS * CMODEL];        // x, permuted tf32
__device__ uint32_t g_wp[4 * CMODEL * CMODEL];   // Wq,Wk,Wv,Wo permuted tf32
__device__ uint32_t g_attnp[MROWS * CMODEL];     // attn output, permuted tf32

// ---------------------------------------------------------------------------
// Helpers
// ---------------------------------------------------------------------------
__device__ __forceinline__ uint32_t smem_u32(const void* p) {
    uint32_t a;
    asm("{ .reg .u64 t; cvta.to.shared.u64 t, %1; cvt.u32.u64 %0, t; }" : "=r"(a) : "l"(p));
    return a;
}
__device__ __forceinline__ void cp_async16(uint32_t s, const void* g) {
    asm volatile("cp.async.ca.shared.global [%0], [%1], 16;" :: "r"(s), "l"(g));
}
#define CP_COMMIT()  asm volatile("cp.async.commit_group;" ::: "memory")
#define CP_WAIT(N)   asm volatile("cp.async.wait_group %0;" :: "n"(N) : "memory")

__device__ __forceinline__ uint32_t f2tf32(float f) {
    uint32_t u;
    asm("cvt.rna.tf32.f32 %0, %1;" : "=r"(u) : "f"(f));
    return u;
}
__device__ __forceinline__ void mma_tf32(float (&d)[4], const uint32_t (&a)[4],
                                         const uint32_t (&b)[2]) {
    asm volatile(
        "mma.sync.aligned.m16n8k8.row.col.f32.tf32.tf32.f32 "
        "{%0,%1,%2,%3}, {%4,%5,%6,%7}, {%8,%9}, {%0,%1,%2,%3};"
        : "+f"(d[0]), "+f"(d[1]), "+f"(d[2]), "+f"(d[3])
        : "r"(a[0]), "r"(a[1]), "r"(a[2]), "r"(a[3]), "r"(b[0]), "r"(b[1]));
}
__device__ __forceinline__ void mma_tf32s(float (&d)[4], uint32_t a0, uint32_t a1,
                                          uint32_t a2, uint32_t a3,
                                          uint32_t b0, uint32_t b1) {
    asm volatile(
        "mma.sync.aligned.m16n8k8.row.col.f32.tf32.tf32.f32 "
        "{%0,%1,%2,%3}, {%4,%5,%6,%7}, {%8,%9}, {%0,%1,%2,%3};"
        : "+f"(d[0]), "+f"(d[1]), "+f"(d[2]), "+f"(d[3])
        : "r"(a0), "r"(a1), "r"(a2), "r"(a3), "r"(b0), "r"(b1));
}

// ---------------------------------------------------------------------------
// Permuted tf32 layout: within each 32-float k-block of a row r,
// element k32 -> word (k32&7)*4 + (k32>>3); the 16B chunk (=k32&7) is XOR-
// swizzled with ((r&1)<<2). One LDS.128 then yields a fragment's 4 k-steps.
// ---------------------------------------------------------------------------
__global__ void permute_tf32(const float* __restrict__ src,
                             uint32_t* __restrict__ dst, int nrows) {
    int idx = blockIdx.x * 256 + threadIdx.x;
    if (idx >= nrows * 256) return;
    int r  = idx >> 8;
    int k  = (idx & 255) * 4;
    float4 v = *reinterpret_cast<const float4*>(&src[(size_t)r * CMODEL + k]);
    float vs[4] = { v.x, v.y, v.z, v.w };
#pragma unroll
    for (int j = 0; j < 4; j++) {
        int kk = k + j, kb = kk >> 5, k32 = kk & 31;
        int chunk = k32 & 7, sub = k32 >> 3;
        int sc = chunk ^ ((r & 1) << 2);
        dst[(size_t)r * CMODEL + kb * 32 + sc * 4 + sub] = f2tf32(vs[j]);
    }
}

// ---------------------------------------------------------------------------
// TF32 mma.sync GEMM on permuted operands: C[m][n] = sum_k A[m][k]*W[n][k]
// CTA tile 256x128, BK=32, 512 threads = 16 warps in 4(M) x 4(N);
// warp tile 64x32. Inner loop: 24 LDS.128 + 64 MMA, zero cvt.
// ---------------------------------------------------------------------------
#define BK 32
#define ATU (256 * 32)               // A tile u32
#define WTU (128 * 32)
#define STAGEU (ATU + WTU)
#define GSMEM_BYTES (2 * STAGEU * 4) // 98304

__device__ __forceinline__ void gemm_body(const uint32_t* __restrict__ A,
                                          const uint32_t* __restrict__ W,
                                          float* __restrict__ C,
                                          const float* __restrict__ freqs,
                                          int m0, int n0, bool rope,
                                          uint32_t* smem) {
    const int K = CMODEL, N = CMODEL;
    uint32_t* As[2] = { smem,        smem + STAGEU };
    uint32_t* Ws[2] = { smem + ATU,  smem + STAGEU + ATU };

    const int tid  = threadIdx.x;
    const int lane = tid & 31;
    const int wid  = tid >> 5;       // 0..15
    const int g    = lane >> 2;
    const int tg   = lane & 3;
    const int wm   = (wid & 3) * 64;
    const int wn   = (wid >> 2) * 32;

    float acc[4][4][4];
#pragma unroll
    for (int mt = 0; mt < 4; mt++)
#pragma unroll
        for (int nt = 0; nt < 4; nt++)
#pragma unroll
            for (int r = 0; r < 4; r++) acc[mt][nt][r] = 0.0f;

    const int ntiles = K / BK;

    auto load_tile = [&](int kt, int stg) {
        const int ko = kt * BK;
#pragma unroll
        for (int i = 0; i < 4; i++) {
            const int f = tid + 512 * i;       // 0..2047
            const int row = f >> 3;
            const int c = (f & 7) * 4;
            cp_async16(smem_u32(&As[stg][row * 32 + c]),
                       &A[(size_t)(m0 + row) * K + ko + c]);
        }
#pragma unroll
        for (int i = 0; i < 2; i++) {
            const int f = tid + 512 * i;       // 0..1023
            const int row = f >> 3;
            const int c = (f & 7) * 4;
            cp_async16(smem_u32(&Ws[stg][row * 32 + c]),
                       &W[(size_t)(n0 + row) * K + ko + c]);
        }
    };

    load_tile(0, 0);
    CP_COMMIT();

    const int swz = (g & 1) << 2;
    const int c0 = (tg ^ swz) << 2;          // u32 offset of chunk tg
    const int c1 = ((tg + 4) ^ swz) << 2;    // chunk tg+4

    for (int kt = 0; kt < ntiles; kt++) {
        const int buf = kt & 1;
        if (kt + 1 < ntiles) {
            load_tile(kt + 1, (kt + 1) & 1);
            CP_COMMIT();
            CP_WAIT(1);
        } else {
            CP_WAIT(0);
        }
        __syncthreads();

        const uint32_t* at = As[buf];
        const uint32_t* wt = Ws[buf];

        uint4 b0v[4], b1v[4];
#pragma unroll
        for (int nt = 0; nt < 4; nt++) {
            const uint32_t* wb = wt + (wn + nt * 8 + g) * 32;
            b0v[nt] = *reinterpret_cast<const uint4*>(wb + c0);
            b1v[nt] = *reinterpret_cast<const uint4*>(wb + c1);
        }

#pragma unroll
        for (int mt = 0; mt < 4; mt++) {
            const uint32_t* ab0 = at + (wm + mt * 16 + g) * 32;
            const uint32_t* ab1 = ab0 + 8 * 32;
            uint4 A0 = *reinterpret_cast<const uint4*>(ab0 + c0);
            uint4 A1 = *reinterpret_cast<const uint4*>(ab1 + c0);
            uint4 A2 = *reinterpret_cast<const uint4*>(ab0 + c1);
            uint4 A3 = *reinterpret_cast<const uint4*>(ab1 + c1);
            const uint32_t* a0p = reinterpret_cast<const uint32_t*>(&A0);
            const uint32_t* a1p = reinterpret_cast<const uint32_t*>(&A1);
            const uint32_t* a2p = reinterpret_cast<const uint32_t*>(&A2);
            const uint32_t* a3p = reinterpret_cast<const uint32_t*>(&A3);
#pragma unroll
            for (int ks = 0; ks < 4; ks++) {
                const uint32_t* b0p0 = reinterpret_cast<const uint32_t*>(&b0v[0]);
#pragma unroll
                for (int nt = 0; nt < 4; nt++) {
                    const uint32_t* bp0 = reinterpret_cast<const uint32_t*>(&b0v[nt]);
                    const uint32_t* bp1 = reinterpret_cast<const uint32_t*>(&b1v[nt]);
                    mma_tf32s(acc[mt][nt], a0p[ks], a1p[ks], a2p[ks], a3p[ks],
                              bp0[ks], bp1[ks]);
                }
                (void)b0p0;
            }
        }
        __syncthreads();
    }

    // epilogue (optionally fused RoPE)
#pragma unroll
    for (int mt = 0; mt < 4; mt++) {
        const int row = m0 + wm + mt * 16 + g;
        const int t0 = row & (SEQ - 1);
        const int t1 = (row + 8) & (SEQ - 1);
#pragma unroll
        for (int nt = 0; nt < 4; nt++) {
            const int col = n0 + wn + nt * 8 + 2 * tg;
            float2 v0 = make_float2(acc[mt][nt][0], acc[mt][nt][1]);
            float2 v1 = make_float2(acc[mt][nt][2], acc[mt][nt][3]);
            if (rope) {
                const int fo = (col & 62);
                float cc0 = freqs[t0 * HDIM + fo], ss0 = freqs[t0 * HDIM + fo + 1];
                float cc1 = freqs[t1 * HDIM + fo], ss1 = freqs[t1 * HDIM + fo + 1];
                v0 = make_float2(v0.x * cc0 - v0.y * ss0, v0.x * ss0 + v0.y * cc0);
                v1 = make_float2(v1.x * cc1 - v1.y * ss1, v1.x * ss1 + v1.y * cc1);
            }
            *reinterpret_cast<float2*>(&C[(size_t)row * N + col]) = v0;
            *reinterpret_cast<float2*>(&C[(size_t)(row + 8) * N + col]) = v1;
        }
    }
}

// Fused QKV + RoPE: grid.x in 0..23 -> (matrix, n-block); grid.y -> m-block
__global__ __launch_bounds__(512, 1) void gemm_qkv(const uint32_t* __restrict__ xp,
                                                   const uint32_t* __restrict__ wp,
                                                   float* __restrict__ q,
                                                   float* __restrict__ k,
                                                   float* __restrict__ v,
                                                   const float* __restrict__ freqs) {
    extern __shared__ uint32_t smem[];
    const int wsel = blockIdx.x >> 3;
    const int n0 = (blockIdx.x & 7) * 128;
    const int m0 = blockIdx.y * 256;
    const uint32_t* W = wp + (size_t)wsel * CMODEL * CMODEL;
    float* C = (wsel == 0) ? q : (wsel == 1) ? k : v;
    gemm_body(xp, W, C, freqs, m0, n0, wsel < 2, smem);
}

__global__ __launch_bounds__(512, 1) void gemm_proj(const uint32_t* __restrict__ attnp,
                                                    const uint32_t* __restrict__ wp,
                                                    float* __restrict__ C) {
    extern __shared__ uint32_t smem[];
    gemm_body(attnp, wp + (size_t)3 * CMODEL * CMODEL, C, nullptr,
              blockIdx.y * 256, blockIdx.x * 128, false, smem);
}

// ---------------------------------------------------------------------------
// Tensor-core flash-attention; epilogue stages O in SMEM then writes
// permuted tf32 COALESCED for gemm_proj.
// ---------------------------------------------------------------------------
#define APAD 68
#define ATILE (64 * APAD)
#define ASMEM_FLOATS (4 * ATILE + 128 * APAD)

__global__ __launch_bounds__(256, 1) void flash_attn_mma(const float* __restrict__ Q,
                                                         const float* __restrict__ K,
                                                         const float* __restrict__ V,
                                                         uint32_t* __restrict__ O) {
    extern __shared__ float sm[];
    float* Ksm[2] = { sm,             sm + 2 * ATILE };
    float* Vsm[2] = { sm + ATILE,     sm + 3 * ATILE };
    float* Ps = sm + 4 * ATILE;

    const int tid  = threadIdx.x;
    const int lane = tid & 31;
    const int wid  = tid >> 5;
    const int g    = lane >> 2;
    const int tg   = lane & 3;

    const int qb = (int)gridDim.x - 1 - (int)blockIdx.x;
    const int h  = blockIdx.y;
    const int b  = blockIdx.z;
    const int q0 = qb * 128;
    const int wrow = wid * 16;
    const int r0g = q0 + wrow + g;
    const int r1g = r0g + 8;

    const float scale = 0.125f;
    uint32_t qf[8][4];
    {
        const float* q0p = Q + (((size_t)b * SEQ + r0g) * NHEAD + h) * HDIM;
        const float* q1p = Q + (((size_t)b * SEQ + r1g) * NHEAD + h) * HDIM;
#pragma unroll
        for (int ks = 0; ks < 8; ks++) {
            const int kc = ks * 8 + tg;
            qf[ks][0] = f2tf32(q0p[kc] * scale);
            qf[ks][1] = f2tf32(q1p[kc] * scale);
            qf[ks][2] = f2tf32(q0p[kc + 4] * scale);
            qf[ks][3] = f2tf32(q1p[kc + 4] * scale);
        }
    }

    float of[8][4];
#pragma unroll
    for (int nt = 0; nt < 8; nt++)
#pragma unroll
        for (int r = 0; r < 4; r++) of[nt][r] = 0.0f;
    float mrow[2] = { -1e30f, -1e30f };
    float lrow[2] = { 0.0f, 0.0f };

    const int ntiles = (q0 + 128) / 64;

    const uint32_t ks0 = smem_u32(Ksm[0]);
    const uint32_t vs0 = smem_u32(Vsm[0]);
    const uint32_t stageB = 2 * ATILE * 4;

    auto prefetch = [&](int t, int s) {
        const int kt = t * 64;
#pragma unroll
        for (int i = 0; i < 4; i++) {
            const int f = tid + 256 * i;
            const int row = f >> 4;
            const int c4 = (f & 15) * 4;
            const size_t gsrc = (((size_t)b * SEQ + kt + row) * NHEAD + h) * HDIM + c4;
            const uint32_t soff = s * stageB + (row * APAD + c4) * 4;
            cp_async16(ks0 + soff, &K[gsrc]);
            cp_async16(vs0 + soff, &V[gsrc]);
        }
    };

    prefetch(0, 0);
    CP_COMMIT();

    for (int t = 0; t < ntiles; t++) {
        const int kt = t * 64;
        if (t + 1 < ntiles) {
            prefetch(t + 1, (t + 1) & 1);
            CP_COMMIT();
            CP_WAIT(1);
        } else {
            CP_WAIT(0);
        }
        __syncthreads();

        const bool skip = kt > q0 + wrow + 15;
        if (!skip) {
            const float* kb = Ksm[t & 1];
            const float* vb = Vsm[t & 1];

            float sacc[8][4];
#pragma unroll
            for (int nt = 0; nt < 8; nt++)
#pragma unroll
                for (int r = 0; r < 4; r++) sacc[nt][r] = 0.0f;

#pragma unroll
            for (int ks = 0; ks < 8; ks++) {
                const int kc = ks * 8 + tg;
#pragma unroll
                for (int nt = 0; nt < 8; nt++) {
                    uint32_t bf[2];
                    bf[0] = f2tf32(kb[(nt * 8 + g) * APAD + kc]);
                    bf[1] = f2tf32(kb[(nt * 8 + g) * APAD + kc + 4]);
                    mma_tf32(sacc[nt], qf[ks], bf);
                }
            }

            if (kt + 63 > q0 + wrow) {
#pragma unroll
                for (int nt = 0; nt < 8; nt++) {
                    const int c = kt + nt * 8 + 2 * tg;
                    if (c > r0g)     sacc[nt][0] = -1e30f;
                    if (c + 1 > r0g) sacc[nt][1] = -1e30f;
                    if (c > r1g)     sacc[nt][2] = -1e30f;
                    if (c + 1 > r1g) sacc[nt][3] = -1e30f;
                }
            }

            float rmax0 = -1e30f, rmax1 = -1e30f;
#pragma unroll
            for (int nt = 0; nt < 8; nt++) {
                rmax0 = fmaxf(rmax0, fmaxf(sacc[nt][0], sacc[nt][1]));
                rmax1 = fmaxf(rmax1, fmaxf(sacc[nt][2], sacc[nt][3]));
            }
            rmax0 = fmaxf(rmax0, __shfl_xor_sync(0xffffffff, rmax0, 1));
            rmax0 = fmaxf(rmax0, __shfl_xor_sync(0xffffffff, rmax0, 2));
            rmax1 = fmaxf(rmax1, __shfl_xor_sync(0xffffffff, rmax1, 1));
            rmax1 = fmaxf(rmax1, __shfl_xor_sync(0xffffffff, rmax1, 2));

            const float mn0 = fmaxf(mrow[0], rmax0);
            const float mn1 = fmaxf(mrow[1], rmax1);
            const float corr0 = __expf(mrow[0] - mn0);
            const float corr1 = __expf(mrow[1] - mn1);
            mrow[0] = mn0; mrow[1] = mn1;

            float rs0 = 0.0f, rs1 = 0.0f;
            float* p0row = &Ps[(wrow + g) * APAD + 2 * tg];
            float* p1row = &Ps[(wrow + g + 8) * APAD + 2 * tg];
#pragma unroll
            for (int nt = 0; nt < 8; nt++) {
                const float e0 = __expf(sacc[nt][0] - mn0);
                const float e1 = __expf(sacc[nt][1] - mn0);
                const float e2 = __expf(sacc[nt][2] - mn1);
                const float e3 = __expf(sacc[nt][3] - mn1);
                rs0 += e0 + e1;
                rs1 += e2 + e3;
                *reinterpret_cast<float2*>(p0row + nt * 8) = make_float2(e0, e1);
                *reinterpret_cast<float2*>(p1row + nt * 8) = make_float2(e2, e3);
            }
            rs0 += __shfl_xor_sync(0xffffffff, rs0, 1);
            rs0 += __shfl_xor_sync(0xffffffff, rs0, 2);
            rs1 += __shfl_xor_sync(0xffffffff, rs1, 1);
            rs1 += __shfl_xor_sync(0xffffffff, rs1, 2);
            lrow[0] = lrow[0] * corr0 + rs0;
            lrow[1] = lrow[1] * corr1 + rs1;

#pragma unroll
            for (int nt = 0; nt < 8; nt++) {
                of[nt][0] *= corr0; of[nt][1] *= corr0;
                of[nt][2] *= corr1; of[nt][3] *= corr1;
            }
            __syncwarp();

#pragma unroll
            for (int ks = 0; ks < 8; ks++) {
                const int kc = ks * 8 + tg;
                uint32_t a[4];
                a[0] = f2tf32(Ps[(wrow + g) * APAD + kc]);
                a[1] = f2tf32(Ps[(wrow + g + 8) * APAD + kc]);
                a[2] = f2tf32(Ps[(wrow + g) * APAD + kc + 4]);
                a[3] = f2tf32(Ps[(wrow + g + 8) * APAD + kc + 4]);
#pragma unroll
                for (int nt = 0; nt < 8; nt++) {
                    uint32_t bf[2];
                    bf[0] = f2tf32(vb[kc * APAD + nt * 8 + g]);
                    bf[1] = f2tf32(vb[(kc + 4) * APAD + nt * 8 + g]);
                    mma_tf32(of[nt], a, bf);
                }
            }
        }
        __syncthreads();
    }

    // ---- epilogue: stage O rows in SMEM, then coalesced permuted stores ----
    const float inv0 = 1.0f / lrow[0];
    const float inv1 = 1.0f / lrow[1];
    {
        float* st0 = &Ps[(wrow + g) * APAD];
        float* st1 = &Ps[(wrow + g + 8) * APAD];
#pragma unroll
        for (int nt = 0; nt < 8; nt++) {
            const int col = nt * 8 + 2 * tg;
            *reinterpret_cast<float2*>(st0 + col) =
                make_float2(of[nt][0] * inv0, of[nt][1] * inv0);
            *reinterpret_cast<float2*>(st1 + col) =
                make_float2(of[nt][2] * inv1, of[nt][3] * inv1);
        }
    }
    __syncwarp();
    // each warp: 16 rows x 64 cols; lane covers 2 u32 per row, one 128B
    // k-block per 32-lane group -> fully coalesced
#pragma unroll
    for (int rr = 0; rr < 16; rr++) {
        const int row = wrow + rr;                 // row within CTA q-tile
        const size_t grow = (size_t)b * SEQ + q0 + row;
        const int sw2 = ((q0 + row) & 1) << 2;
#pragma unroll
        for (int j = 0; j < 2; j++) {
            const int col = lane + 32 * j;         // 0..63
            const int k32 = col & 31;
            const int word = ((k32 & 7) ^ sw2) * 4 + (k32 >> 3);
            const int kb = h * 2 + j;
            O[grow * CMODEL + kb * 32 + word] = f2tf32(Ps[row * APAD + col]);
        }
    }
}

// ---------------------------------------------------------------------------
// kernel_launch
// ---------------------------------------------------------------------------
extern "C" void kernel_launch(void* const* d_in, const int* in_sizes, int n_in,
                              void* d_out, int out_size) {
    const float* x     = (const float*)d_in[0];
    const float* freqs = (const float*)d_in[1];
    const float* Wq    = (const float*)d_in[2];
    const float* Wk    = (const float*)d_in[3];
    const float* Wv    = (const float*)d_in[4];
    const float* Wo    = (const float*)d_in[5];
    float* out = (float*)d_out;

    float *q = nullptr, *k = nullptr, *v = nullptr;
    uint32_t *xp = nullptr, *wp = nullptr, *attnp = nullptr;
    cudaGetSymbolAddress((void**)&q,     g_q);
    cudaGetSymbolAddress((void**)&k,     g_k);
    cudaGetSymbolAddress((void**)&v,     g_v);
    cudaGetSymbolAddress((void**)&xp,    g_xp);
    cudaGetSymbolAddress((void**)&wp,    g_wp);
    cudaGetSymbolAddress((void**)&attnp, g_attnp);

    cudaFuncSetAttribute(gemm_qkv,  cudaFuncAttributeMaxDynamicSharedMemorySize, GSMEM_BYTES);
    cudaFuncSetAttribute(gemm_proj, cudaFuncAttributeMaxDynamicSharedMemorySize, GSMEM_BYTES);
    const int asmem = ASMEM_FLOATS * sizeof(float);
    cudaFuncSetAttribute(flash_attn_mma, cudaFuncAttributeMaxDynamicSharedMemorySize, asmem);

    // Pre-pass: convert+permute x and all four weight matrices to tf32
    permute_tf32<<<MROWS, 256>>>(x,  xp, MROWS);
    permute_tf32<<<CMODEL, 256>>>(Wq, wp + 0 * (size_t)CMODEL * CMODEL, CMODEL);
    permute_tf32<<<CMODEL, 256>>>(Wk, wp + 1 * (size_t)CMODEL * CMODEL, CMODEL);
    permute_tf32<<<CMODEL, 256>>>(Wv, wp + 2 * (size_t)CMODEL * CMODEL, CMODEL);
    permute_tf32<<<CMODEL, 256>>>(Wo, wp + 3 * (size_t)CMODEL * CMODEL, CMODEL);

    gemm_qkv<<<dim3(24, MROWS / 256), 512, GSMEM_BYTES>>>(xp, wp, q, k, v, freqs);

    {
        dim3 agrid(SEQ / 128, NHEAD, BATCH);
        flash_attn_mma<<<agrid, 256, asmem>>>(q, k, v, attnp);
    }

    gemm_proj<<<dim3(CMODEL / 128, MROWS / 256), 512, GSMEM_BYTES>>>(attnp, wp, out);
}

// round 9
// speedup vs baseline: 1.1620x; 1.1620x over previous
#include <cuda_runtime.h>
#include <cuda_bf16.h>
#include <cstdint>
#include <math.h>

// Problem constants
#define BATCH 2
#define SEQ   2048
#define CMODEL 1024
#define NHEAD 16
#define HDIM  64
#define MROWS (BATCH * SEQ)   // 4096

// ---------------------------------------------------------------------------
// Scratch
// ---------------------------------------------------------------------------
__device__ float g_q[MROWS * CMODEL];
__device__ float g_k[MROWS * CMODEL];
__device__ float g_v[MROWS * CMODEL];
__device__ float g_attn[MROWS * CMODEL];

// ---------------------------------------------------------------------------
// Helpers
// ---------------------------------------------------------------------------
__device__ __forceinline__ uint32_t smem_u32(const void* p) {
    uint32_t a;
    asm("{ .reg .u64 t; cvta.to.shared.u64 t, %1; cvt.u32.u64 %0, t; }" : "=r"(a) : "l"(p));
    return a;
}
__device__ __forceinline__ void cp_async16(uint32_t s, const void* g) {
    asm volatile("cp.async.ca.shared.global [%0], [%1], 16;" :: "r"(s), "l"(g));
}
#define CP_COMMIT()  asm volatile("cp.async.commit_group;" ::: "memory")
#define CP_WAIT(N)   asm volatile("cp.async.wait_group %0;" :: "n"(N) : "memory")

__device__ __forceinline__ uint32_t f2tf32(float f) {
    uint32_t u;
    asm("cvt.rna.tf32.f32 %0, %1;" : "=r"(u) : "f"(f));
    return u;
}
__device__ __forceinline__ void mma_tf32(float (&d)[4], const uint32_t (&a)[4],
                                         const uint32_t (&b)[2]) {
    asm volatile(
        "mma.sync.aligned.m16n8k8.row.col.f32.tf32.tf32.f32 "
        "{%0,%1,%2,%3}, {%4,%5,%6,%7}, {%8,%9}, {%0,%1,%2,%3};"
        : "+f"(d[0]), "+f"(d[1]), "+f"(d[2]), "+f"(d[3])
        : "r"(a[0]), "r"(a[1]), "r"(a[2]), "r"(a[3]), "r"(b[0]), "r"(b[1]));
}

// ---------------------------------------------------------------------------
// TF32 mma.sync GEMM body (R6 structure): C[m][n] = sum_k A[m][k] * W[n][k]
// CTA tile 256x128, BK=32, 512 threads = 16 warps in 4(M) x 4(N);
// warp tile 64x32. Optional fused RoPE; optional tf32-rounding of outputs.
// ---------------------------------------------------------------------------
#define BK 32
#define KST 36                       // padded row stride (floats)
#define ATF (256 * KST)
#define WTF (128 * KST)
#define STAGEF (ATF + WTF)
#define G2SMEM_FLOATS (2 * STAGEF)   // 110592 bytes

__device__ __forceinline__ void gemm_body(const float* __restrict__ A,
                                          const float* __restrict__ W,
                                          float* __restrict__ C,
                                          const float* __restrict__ freqs,
                                          int m0, int n0, bool rope, bool roundout,
                                          float* smem) {
    const int K = CMODEL, N = CMODEL;
    float* As[2] = { smem,          smem + STAGEF };
    float* Ws[2] = { smem + ATF,    smem + STAGEF + ATF };

    const int tid  = threadIdx.x;
    const int lane = tid & 31;
    const int wid  = tid >> 5;       // 0..15
    const int g    = lane >> 2;
    const int tg   = lane & 3;
    const int wm   = (wid & 3) * 64;
    const int wn   = (wid >> 2) * 32;

    float acc[4][4][4];
#pragma unroll
    for (int mt = 0; mt < 4; mt++)
#pragma unroll
        for (int nt = 0; nt < 4; nt++)
#pragma unroll
            for (int r = 0; r < 4; r++) acc[mt][nt][r] = 0.0f;

    const int ntiles = K / BK;

    auto load_tile = [&](int kt, int stg) {
        const int ko = kt * BK;
#pragma unroll
        for (int i = 0; i < 4; i++) {
            const int f = tid + 512 * i;       // 0..2047
            const int row = f >> 3;
            const int c4 = (f & 7) * 4;
            cp_async16(smem_u32(&As[stg][row * KST + c4]),
                       &A[(size_t)(m0 + row) * K + ko + c4]);
        }
#pragma unroll
        for (int i = 0; i < 2; i++) {
            const int f = tid + 512 * i;       // 0..1023
            const int row = f >> 3;
            const int c4 = (f & 7) * 4;
            cp_async16(smem_u32(&Ws[stg][row * KST + c4]),
                       &W[(size_t)(n0 + row) * K + ko + c4]);
        }
    };

    load_tile(0, 0);
    CP_COMMIT();

    for (int kt = 0; kt < ntiles; kt++) {
        const int buf = kt & 1;
        if (kt + 1 < ntiles) {
            load_tile(kt + 1, (kt + 1) & 1);
            CP_COMMIT();
            CP_WAIT(1);
        } else {
            CP_WAIT(0);
        }
        __syncthreads();

        const float* at = As[buf];
        const float* wt = Ws[buf];
#pragma unroll
        for (int ks = 0; ks < 4; ks++) {
            const int kc = ks * 8 + tg;
            uint32_t a[4][4];
#pragma unroll
            for (int mt = 0; mt < 4; mt++) {
                const int r0 = (wm + mt * 16 + g) * KST;
                a[mt][0] = f2tf32(at[r0 + kc]);
                a[mt][1] = f2tf32(at[r0 + 8 * KST + kc]);
                a[mt][2] = f2tf32(at[r0 + kc + 4]);
                a[mt][3] = f2tf32(at[r0 + 8 * KST + kc + 4]);
            }
            uint32_t b[4][2];
#pragma unroll
            for (int nt = 0; nt < 4; nt++) {
                const int r0 = (wn + nt * 8 + g) * KST;
                b[nt][0] = f2tf32(wt[r0 + kc]);
                b[nt][1] = f2tf32(wt[r0 + kc + 4]);
            }
#pragma unroll
            for (int mt = 0; mt < 4; mt++)
#pragma unroll
                for (int nt = 0; nt < 4; nt++)
                    mma_tf32(acc[mt][nt], a[mt], b[nt]);
        }
        __syncthreads();
    }

    // epilogue: optional fused RoPE, optional tf32 rounding of stored values
#pragma unroll
    for (int mt = 0; mt < 4; mt++) {
        const int row = m0 + wm + mt * 16 + g;
        const int t0 = row & (SEQ - 1);
        const int t1 = (row + 8) & (SEQ - 1);
#pragma unroll
        for (int nt = 0; nt < 4; nt++) {
            const int col = n0 + wn + nt * 8 + 2 * tg;
            float2 v0 = make_float2(acc[mt][nt][0], acc[mt][nt][1]);
            float2 v1 = make_float2(acc[mt][nt][2], acc[mt][nt][3]);
            if (rope) {
                const int fo = (col & 62);
                float cc0 = freqs[t0 * HDIM + fo], ss0 = freqs[t0 * HDIM + fo + 1];
                float cc1 = freqs[t1 * HDIM + fo], ss1 = freqs[t1 * HDIM + fo + 1];
                v0 = make_float2(v0.x * cc0 - v0.y * ss0, v0.x * ss0 + v0.y * cc0);
                v1 = make_float2(v1.x * cc1 - v1.y * ss1, v1.x * ss1 + v1.y * cc1);
            }
            if (roundout) {
                v0.x = __uint_as_float(f2tf32(v0.x));
                v0.y = __uint_as_float(f2tf32(v0.y));
                v1.x = __uint_as_float(f2tf32(v1.x));
                v1.y = __uint_as_float(f2tf32(v1.y));
            }
            *reinterpret_cast<float2*>(&C[(size_t)row * N + col]) = v0;
            *reinterpret_cast<float2*>(&C[(size_t)(row + 8) * N + col]) = v1;
        }
    }
}

// Fused QKV + RoPE, outputs tf32-rounded for cvt-free attention
__global__ __launch_bounds__(512, 1) void gemm_qkv(const float* __restrict__ x,
                                                   const float* __restrict__ Wq,
                                                   const float* __restrict__ Wk,
                                                   const float* __restrict__ Wv,
                                                   float* __restrict__ q,
                                                   float* __restrict__ k,
                                                   float* __restrict__ v,
                                                   const float* __restrict__ freqs) {
    extern __shared__ float smem[];
    const int wsel = blockIdx.x >> 3;
    const int n0 = (blockIdx.x & 7) * 128;
    const int m0 = blockIdx.y * 256;
    const float* W = (wsel == 0) ? Wq : (wsel == 1) ? Wk : Wv;
    float* C = (wsel == 0) ? q : (wsel == 1) ? k : v;
    gemm_body(x, W, C, freqs, m0, n0, wsel < 2, true, smem);
}

__global__ __launch_bounds__(512, 1) void gemm_proj(const float* __restrict__ A,
                                                    const float* __restrict__ W,
                                                    float* __restrict__ C) {
    extern __shared__ float smem[];
    gemm_body(A, W, C, nullptr, blockIdx.y * 256, blockIdx.x * 128, false, false, smem);
}

// ---------------------------------------------------------------------------
// Tensor-core flash-attention, cvt-free: Q/K/V arrive pre-rounded to tf32,
// operand fragments are raw bit loads. P rounded once at SMEM store.
// ---------------------------------------------------------------------------
#define APAD 68
#define ATILE (64 * APAD)
#define ASMEM_FLOATS (4 * ATILE + 128 * APAD)

__global__ __launch_bounds__(256, 1) void flash_attn_mma(const float* __restrict__ Q,
                                                         const float* __restrict__ K,
                                                         const float* __restrict__ V,
                                                         float* __restrict__ O) {
    extern __shared__ float sm[];
    float* Ksm[2] = { sm,             sm + 2 * ATILE };
    float* Vsm[2] = { sm + ATILE,     sm + 3 * ATILE };
    float* Ps = sm + 4 * ATILE;

    const int tid  = threadIdx.x;
    const int lane = tid & 31;
    const int wid  = tid >> 5;
    const int g    = lane >> 2;
    const int tg   = lane & 3;

    const int qb = (int)gridDim.x - 1 - (int)blockIdx.x;
    const int h  = blockIdx.y;
    const int b  = blockIdx.z;
    const int q0 = qb * 128;
    const int wrow = wid * 16;
    const int r0g = q0 + wrow + g;
    const int r1g = r0g + 8;

    const float scale = 0.125f;   // pow2: tf32-exact scaling
    uint32_t qf[8][4];
    {
        const float* q0p = Q + (((size_t)b * SEQ + r0g) * NHEAD + h) * HDIM;
        const float* q1p = Q + (((size_t)b * SEQ + r1g) * NHEAD + h) * HDIM;
#pragma unroll
        for (int ks = 0; ks < 8; ks++) {
            const int kc = ks * 8 + tg;
            qf[ks][0] = __float_as_uint(q0p[kc] * scale);
            qf[ks][1] = __float_as_uint(q1p[kc] * scale);
            qf[ks][2] = __float_as_uint(q0p[kc + 4] * scale);
            qf[ks][3] = __float_as_uint(q1p[kc + 4] * scale);
        }
    }

    float of[8][4];
#pragma unroll
    for (int nt = 0; nt < 8; nt++)
#pragma unroll
        for (int r = 0; r < 4; r++) of[nt][r] = 0.0f;
    float mrow[2] = { -1e30f, -1e30f };
    float lrow[2] = { 0.0f, 0.0f };

    const int ntiles = (q0 + 128) / 64;

    const uint32_t ks0 = smem_u32(Ksm[0]);
    const uint32_t vs0 = smem_u32(Vsm[0]);
    const uint32_t stageB = 2 * ATILE * 4;

    auto prefetch = [&](int t, int s) {
        const int kt = t * 64;
#pragma unroll
        for (int i = 0; i < 4; i++) {
            const int f = tid + 256 * i;
            const int row = f >> 4;
            const int c4 = (f & 15) * 4;
            const size_t gsrc = (((size_t)b * SEQ + kt + row) * NHEAD + h) * HDIM + c4;
            const uint32_t soff = s * stageB + (row * APAD + c4) * 4;
            cp_async16(ks0 + soff, &K[gsrc]);
            cp_async16(vs0 + soff, &V[gsrc]);
        }
    };

    prefetch(0, 0);
    CP_COMMIT();

    for (int t = 0; t < ntiles; t++) {
        const int kt = t * 64;
        if (t + 1 < ntiles) {
            prefetch(t + 1, (t + 1) & 1);
            CP_COMMIT();
            CP_WAIT(1);
        } else {
            CP_WAIT(0);
        }
        __syncthreads();

        const bool skip = kt > q0 + wrow + 15;
        if (!skip) {
            const float* kb = Ksm[t & 1];
            const float* vb = Vsm[t & 1];

            float sacc[8][4];
#pragma unroll
            for (int nt = 0; nt < 8; nt++)
#pragma unroll
                for (int r = 0; r < 4; r++) sacc[nt][r] = 0.0f;

#pragma unroll
            for (int ks = 0; ks < 8; ks++) {
                const int kc = ks * 8 + tg;
#pragma unroll
                for (int nt = 0; nt < 8; nt++) {
                    uint32_t bf[2];
                    bf[0] = __float_as_uint(kb[(nt * 8 + g) * APAD + kc]);
                    bf[1] = __float_as_uint(kb[(nt * 8 + g) * APAD + kc + 4]);
                    mma_tf32(sacc[nt], qf[ks], bf);
                }
            }

            if (kt + 63 > q0 + wrow) {
#pragma unroll
                for (int nt = 0; nt < 8; nt++) {
                    const int c = kt + nt * 8 + 2 * tg;
                    if (c > r0g)     sacc[nt][0] = -1e30f;
                    if (c + 1 > r0g) sacc[nt][1] = -1e30f;
                    if (c > r1g)     sacc[nt][2] = -1e30f;
                    if (c + 1 > r1g) sacc[nt][3] = -1e30f;
                }
            }

            float rmax0 = -1e30f, rmax1 = -1e30f;
#pragma unroll
            for (int nt = 0; nt < 8; nt++) {
                rmax0 = fmaxf(rmax0, fmaxf(sacc[nt][0], sacc[nt][1]));
                rmax1 = fmaxf(rmax1, fmaxf(sacc[nt][2], sacc[nt][3]));
            }
            rmax0 = fmaxf(rmax0, __shfl_xor_sync(0xffffffff, rmax0, 1));
            rmax0 = fmaxf(rmax0, __shfl_xor_sync(0xffffffff, rmax0, 2));
            rmax1 = fmaxf(rmax1, __shfl_xor_sync(0xffffffff, rmax1, 1));
            rmax1 = fmaxf(rmax1, __shfl_xor_sync(0xffffffff, rmax1, 2));

            const float mn0 = fmaxf(mrow[0], rmax0);
            const float mn1 = fmaxf(mrow[1], rmax1);
            const float corr0 = __expf(mrow[0] - mn0);
            const float corr1 = __expf(mrow[1] - mn1);
            mrow[0] = mn0; mrow[1] = mn1;

            float rs0 = 0.0f, rs1 = 0.0f;
            float* p0row = &Ps[(wrow + g) * APAD + 2 * tg];
            float* p1row = &Ps[(wrow + g + 8) * APAD + 2 * tg];
#pragma unroll
            for (int nt = 0; nt < 8; nt++) {
                const float e0 = __expf(sacc[nt][0] - mn0);
                const float e1 = __expf(sacc[nt][1] - mn0);
                const float e2 = __expf(sacc[nt][2] - mn1);
                const float e3 = __expf(sacc[nt][3] - mn1);
                rs0 += e0 + e1;
                rs1 += e2 + e3;
                *reinterpret_cast<float2*>(p0row + nt * 8) =
                    make_float2(__uint_as_float(f2tf32(e0)), __uint_as_float(f2tf32(e1)));
                *reinterpret_cast<float2*>(p1row + nt * 8) =
                    make_float2(__uint_as_float(f2tf32(e2)), __uint_as_float(f2tf32(e3)));
            }
            rs0 += __shfl_xor_sync(0xffffffff, rs0, 1);
            rs0 += __shfl_xor_sync(0xffffffff, rs0, 2);
            rs1 += __shfl_xor_sync(0xffffffff, rs1, 1);
            rs1 += __shfl_xor_sync(0xffffffff, rs1, 2);
            lrow[0] = lrow[0] * corr0 + rs0;
            lrow[1] = lrow[1] * corr1 + rs1;

#pragma unroll
            for (int nt = 0; nt < 8; nt++) {
                of[nt][0] *= corr0; of[nt][1] *= corr0;
                of[nt][2] *= corr1; of[nt][3] *= corr1;
            }
            __syncwarp();

#pragma unroll
            for (int ks = 0; ks < 8; ks++) {
                const int kc = ks * 8 + tg;
                uint32_t a[4];
                a[0] = __float_as_uint(Ps[(wrow + g) * APAD + kc]);
                a[1] = __float_as_uint(Ps[(wrow + g + 8) * APAD + kc]);
                a[2] = __float_as_uint(Ps[(wrow + g) * APAD + kc + 4]);
                a[3] = __float_as_uint(Ps[(wrow + g + 8) * APAD + kc + 4]);
#pragma unroll
                for (int nt = 0; nt < 8; nt++) {
                    uint32_t bf[2];
                    bf[0] = __float_as_uint(vb[kc * APAD + nt * 8 + g]);
                    bf[1] = __float_as_uint(vb[(kc + 4) * APAD + nt * 8 + g]);
                    mma_tf32(of[nt], a, bf);
                }
            }
        }
        __syncthreads();
    }

    const float inv0 = 1.0f / lrow[0];
    const float inv1 = 1.0f / lrow[1];
    float* o0 = O + (((size_t)b * SEQ + r0g) * NHEAD + h) * HDIM;
    float* o1 = O + (((size_t)b * SEQ + r1g) * NHEAD + h) * HDIM;
#pragma unroll
    for (int nt = 0; nt < 8; nt++) {
        const int col = nt * 8 + 2 * tg;
        *reinterpret_cast<float2*>(o0 + col) = make_float2(of[nt][0] * inv0, of[nt][1] * inv0);
        *reinterpret_cast<float2*>(o1 + col) = make_float2(of[nt][2] * inv1, of[nt][3] * inv1);
    }
}

// ---------------------------------------------------------------------------
// kernel_launch
// ---------------------------------------------------------------------------
extern "C" void kernel_launch(void* const* d_in, const int* in_sizes, int n_in,
                              void* d_out, int out_size) {
    const float* x     = (const float*)d_in[0];
    const float* freqs = (const float*)d_in[1];
    const float* Wq    = (const float*)d_in[2];
    const float* Wk    = (const float*)d_in[3];
    const float* Wv    = (const float*)d_in[4];
    const float* Wo    = (const float*)d_in[5];
    float* out = (float*)d_out;

    float *q = nullptr, *k = nullptr, *v = nullptr, *attn = nullptr;
    cudaGetSymbolAddress((void**)&q,    g_q);
    cudaGetSymbolAddress((void**)&k,    g_k);
    cudaGetSymbolAddress((void**)&v,    g_v);
    cudaGetSymbolAddress((void**)&attn, g_attn);

    const int gsmem = G2SMEM_FLOATS * sizeof(float);   // 110592
    cudaFuncSetAttribute(gemm_qkv,  cudaFuncAttributeMaxDynamicSharedMemorySize, gsmem);
    cudaFuncSetAttribute(gemm_proj, cudaFuncAttributeMaxDynamicSharedMemorySize, gsmem);
    const int asmem = ASMEM_FLOATS * sizeof(float);    // 104448
    cudaFuncSetAttribute(flash_attn_mma, cudaFuncAttributeMaxDynamicSharedMemorySize, asmem);

    gemm_qkv<<<dim3(24, MROWS / 256), 512, gsmem>>>(x, Wq, Wk, Wv, q, k, v, freqs);

    {
        dim3 agrid(SEQ / 128, NHEAD, BATCH);
        flash_attn_mma<<<agrid, 256, asmem>>>(q, k, v, attn);
    }

    gemm_proj<<<dim3(CMODEL / 128, MROWS / 256), 512, gsmem>>>(attn, Wo, out);
}